// round 5
// baseline (speedup 1.0000x reference)
#include <cuda_runtime.h>
#include <cuda_fp16.h>
#include <cstdint>

#define B_  4
#define T_  400
#define U_  64
#define E_  320
#define INNER_ 512
#define VOCAB_ 1024
#define BT_ (B_*T_)      // 1600
#define BU_ (B_*U_)      // 256
#define BTU_ (B_*T_*U_)  // 102400

// Scratch (no allocations allowed -> __device__ globals)
__device__ __half g_Pench[BT_*INNER_];    // 1.6 MB fp16 enc projection
__device__ __half g_Pdech[BU_*INNER_];    // 256 KB fp16 dec projection (+b1 folded)
__device__ __half g_W2h[VOCAB_*INNER_];   // 1.0 MB fp16 W2

// ===========================================================================
// Prologue: proj GEMM (M=64,N=64,K=32 tiles; 232 CTAs) + W2 convert (32 CTAs)
// fused into one launch. 256 thr, thread tile 4x4.
// ===========================================================================
__global__ __launch_bounds__(256) void prologue_kernel(
    const float* __restrict__ enc, const float* __restrict__ dec,
    const float* __restrict__ W1, const float* __restrict__ b1,
    const float* __restrict__ W2)
{
    int cb = blockIdx.x;

    // ---- tail CTAs: W2 fp32 -> fp16 ----
    if (cb >= 232) {
        int seg = cb - 232;                       // 0..31
        int base = seg * 16384;                   // floats
        int tid = threadIdx.x;
        for (int i = tid * 2; i < 16384; i += 512) {
            float2 v = *(const float2*)(W2 + base + i);
            *(__half2*)(g_W2h + base + i) = __floats2half2_rn(v.x, v.y);
        }
        return;
    }

    __shared__ float sx[32 * 68];    // [k][m]
    __shared__ float sw[32 * 68];    // [k][n]
    bool isEnc = cb < 200;
    const float* X; int mt, nt, coff;
    if (isEnc) { mt = cb >> 3;         nt = cb & 7;         X = enc; coff = 0;  }
    else       { mt = (cb - 200) >> 3; nt = (cb - 200) & 7; X = dec; coff = E_; }
    int row0 = mt * 64, col0 = nt * 64;

    int tid = threadIdx.x, tx = tid & 15, ty = tid >> 4;
    float acc[4][4];
    #pragma unroll
    for (int r = 0; r < 4; r++)
        #pragma unroll
        for (int c = 0; c < 4; c++) acc[r][c] = 0.f;

    for (int k0 = 0; k0 < E_; k0 += 32) {
        __syncthreads();
        #pragma unroll
        for (int it = 0; it < 8; it++) {
            int i = tid + it * 256;
            int r = i >> 5, k = i & 31;
            sx[k * 68 + r] = X[(row0 + r) * E_ + k0 + k];
        }
        #pragma unroll
        for (int it = 0; it < 8; it++) {
            int i = tid + it * 256;
            int n = i >> 5, k = i & 31;
            sw[k * 68 + n] = W1[(col0 + n) * (2 * E_) + coff + k0 + k];
        }
        __syncthreads();
        #pragma unroll 8
        for (int k = 0; k < 32; k++) {
            float4 xv = *(const float4*)&sx[k * 68 + ty * 4];
            float4 wv = *(const float4*)&sw[k * 68 + tx * 4];
            float xr[4] = {xv.x, xv.y, xv.z, xv.w};
            float wr[4] = {wv.x, wv.y, wv.z, wv.w};
            #pragma unroll
            for (int r = 0; r < 4; r++)
                #pragma unroll
                for (int c = 0; c < 4; c++)
                    acc[r][c] = fmaf(xr[r], wr[c], acc[r][c]);
        }
    }

    __half* P = isEnc ? g_Pench : g_Pdech;
    #pragma unroll
    for (int r = 0; r < 4; r++) {
        int gr = row0 + ty * 4 + r;
        int cbase = col0 + tx * 4;
        #pragma unroll
        for (int c = 0; c < 4; c += 2) {
            float v0 = acc[r][c], v1 = acc[r][c + 1];
            if (!isEnc) { v0 += b1[cbase + c]; v1 += b1[cbase + c + 1]; }
            *(__half2*)(P + gr * INNER_ + cbase + c) = __floats2half2_rn(v0, v1);
        }
    }
}

// ===========================================================================
// Main fused kernel. Per CTA: M=64 rows (single bt; u = r). 1600 CTAs for
// near-perfect SM balance (10.81 avg vs 11 max tiles/SM).
// hs[64][512] fp16 = tanh(pe+pd); 32 W2 chunks (256 vocab x 64 k) double-
// buffered via cp.async; m16n8k16 HMMA fp32 acc; +b2 epilogue per vocab tile.
// ===========================================================================
#define HS_STRIDE 520   // halves
#define WS_STRIDE 72    // halves
#define WS_HALVES (256 * WS_STRIDE)
#define SMEM_BYTES ((64 * HS_STRIDE + 2 * WS_HALVES) * (int)sizeof(__half))  // 140288

__device__ __forceinline__ uint32_t smem_u32(const void* p) {
    uint32_t a;
    asm("{ .reg .u64 t; cvta.to.shared.u64 t, %1; cvt.u32.u64 %0, t; }" : "=r"(a) : "l"(p));
    return a;
}
__device__ __forceinline__ uint32_t tanh2(uint32_t x) {
    uint32_t y; asm("tanh.approx.f16x2 %0, %1;" : "=r"(y) : "r"(x)); return y;
}
__device__ __forceinline__ void cp16(uint32_t dst, const void* src) {
    asm volatile("cp.async.cg.shared.global [%0], [%1], 16;" :: "r"(dst), "l"(src) : "memory");
}
__device__ __forceinline__ void cp_commit() {
    asm volatile("cp.async.commit_group;" ::: "memory");
}
__device__ __forceinline__ void mma16816(float* d, const uint32_t* a, const uint32_t* b) {
    asm volatile(
        "mma.sync.aligned.m16n8k16.row.col.f32.f16.f16.f32 "
        "{%0,%1,%2,%3}, {%4,%5,%6,%7}, {%8,%9}, {%0,%1,%2,%3};\n"
        : "+f"(d[0]), "+f"(d[1]), "+f"(d[2]), "+f"(d[3])
        : "r"(a[0]), "r"(a[1]), "r"(a[2]), "r"(a[3]), "r"(b[0]), "r"(b[1]));
}

// stage one chunk (vt, kc): 256 vocab rows x 64 k-halves, 4x cp.async 16B/thr
__device__ __forceinline__ void stage_chunk(uint32_t ws_u32, int chunk, int tid) {
    int vt = chunk >> 3, kc = chunk & 7;
    #pragma unroll
    for (int it = 0; it < 4; it++) {
        int i = tid + it * 512;
        int n = i >> 3, c8 = i & 7;
        cp16(ws_u32 + (n * WS_STRIDE + c8 * 8) * 2,
             g_W2h + (vt * 256 + n) * INNER_ + kc * 64 + c8 * 8);
    }
    cp_commit();
}

__global__ __launch_bounds__(512, 1) void joint_kernel(
    const float* __restrict__ b2, float* __restrict__ out)
{
    extern __shared__ __half smem[];
    __half* hs  = smem;                                  // [64][HS_STRIDE]
    __half* ws0 = smem + 64 * HS_STRIDE;                 // [256][WS_STRIDE]
    __half* ws1 = ws0 + WS_HALVES;

    int tid = threadIdx.x, lane = tid & 31, warp = tid >> 5;
    int row0 = blockIdx.x * 64;
    int b    = row0 / (T_ * U_);
    int bt   = row0 >> 6;                                // constant per CTA

    uint32_t ws_u32[2] = { smem_u32(ws0), smem_u32(ws1) };

    // prefetch chunk 0 (overlaps phase-1 tanh fill)
    stage_chunk(ws_u32[0], 0, tid);

    // ---- Phase 1: hs = tanh(pe + pd) fp16; pe is one row, loaded once ----
    {
        const uint32_t* PE = (const uint32_t*)g_Pench;
        const uint32_t* PD = (const uint32_t*)g_Pdech;
        int j = tid & 255;                               // half2 column
        uint32_t pe = PE[bt * 256 + j];
        #pragma unroll 4
        for (int r = tid >> 8; r < 64; r += 2) {
            uint32_t pd = PD[(b * U_ + r) * 256 + j];
            __half2 s = __hadd2(*(__half2*)&pe, *(__half2*)&pd);
            *(uint32_t*)(hs + r * HS_STRIDE + j * 2) = tanh2(*(uint32_t*)&s);
        }
    }

    int wm = warp & 1;                 // 2 row groups of 32
    int wn = warp >> 1;                // 8 vocab groups of 32
    int arow = wm * 32 + (lane >> 2);
    int acb  = (lane & 3) * 2;
    int bnb  = wn * 32 + (lane >> 2);

    float acc[2][4][4];
    #pragma unroll
    for (int mi = 0; mi < 2; mi++)
        #pragma unroll
        for (int ni = 0; ni < 4; ni++)
            #pragma unroll
            for (int q = 0; q < 4; q++) acc[mi][ni][q] = 0.f;

    for (int ch = 0; ch < 32; ch++) {
        int vt = ch >> 3, kc = ch & 7;
        __syncthreads();   // prev compute done (or phase-1 on ch==0)
        if (ch + 1 < 32) stage_chunk(ws_u32[(ch + 1) & 1], ch + 1, tid);
        if (ch + 1 < 32) asm volatile("cp.async.wait_group 1;" ::: "memory");
        else             asm volatile("cp.async.wait_group 0;" ::: "memory");
        __syncthreads();   // chunk ch visible to all

        const __half* ws = (ch & 1) ? ws1 : ws0;

        #pragma unroll
        for (int ks = 0; ks < 64; ks += 16) {
            int kx = kc * 64 + ks + acb;     // hs column (global k)
            uint32_t a[2][4];
            #pragma unroll
            for (int mi = 0; mi < 2; mi++) {
                const __half* base  = hs + (arow + mi * 16) * HS_STRIDE;
                const __half* base8 = base + 8 * HS_STRIDE;
                a[mi][0] = *(const uint32_t*)(base  + kx);
                a[mi][1] = *(const uint32_t*)(base8 + kx);
                a[mi][2] = *(const uint32_t*)(base  + kx + 8);
                a[mi][3] = *(const uint32_t*)(base8 + kx + 8);
            }
            uint32_t bf[4][2];
            #pragma unroll
            for (int ni = 0; ni < 4; ni++) {
                const __half* wb = ws + (bnb + ni * 8) * WS_STRIDE + ks + acb;
                bf[ni][0] = *(const uint32_t*)(wb);
                bf[ni][1] = *(const uint32_t*)(wb + 8);
            }
            #pragma unroll
            for (int mi = 0; mi < 2; mi++)
                #pragma unroll
                for (int ni = 0; ni < 4; ni++)
                    mma16816(acc[mi][ni], a[mi], bf[ni]);
        }

        if (kc == 7) {
            // ---- Epilogue for vt: += b2, store fp32, reset acc ----
            #pragma unroll
            for (int mi = 0; mi < 2; mi++) {
                #pragma unroll
                for (int ni = 0; ni < 4; ni++) {
                    int m = row0 + wm * 32 + mi * 16 + (lane >> 2);
                    int n = vt * 256 + wn * 32 + ni * 8 + (lane & 3) * 2;
                    float2 bb = *(const float2*)(b2 + n);
                    float2 v0 = make_float2(acc[mi][ni][0] + bb.x, acc[mi][ni][1] + bb.y);
                    float2 v1 = make_float2(acc[mi][ni][2] + bb.x, acc[mi][ni][3] + bb.y);
                    *(float2*)(out + (size_t)m       * VOCAB_ + n) = v0;
                    *(float2*)(out + (size_t)(m + 8) * VOCAB_ + n) = v1;
                    #pragma unroll
                    for (int q = 0; q < 4; q++) acc[mi][ni][q] = 0.f;
                }
            }
        }
    }
}

// ===========================================================================
extern "C" void kernel_launch(void* const* d_in, const int* in_sizes, int n_in,
                              void* d_out, int out_size)
{
    const float* enc = (const float*)d_in[0];
    const float* dec = (const float*)d_in[1];
    const float* W1  = (const float*)d_in[2];
    const float* b1  = (const float*)d_in[3];
    const float* W2  = (const float*)d_in[4];
    const float* b2  = (const float*)d_in[5];
    float* out = (float*)d_out;

    cudaFuncSetAttribute(joint_kernel,
                         cudaFuncAttributeMaxDynamicSharedMemorySize, SMEM_BYTES);

    prologue_kernel<<<264, 256>>>(enc, dec, W1, b1, W2);
    joint_kernel<<<BTU_/64, 512, SMEM_BYTES>>>(b2, out);
}

// round 7
// speedup vs baseline: 1.0953x; 1.0953x over previous
#include <cuda_runtime.h>
#include <cuda_fp16.h>
#include <cstdint>

#define B_  4
#define T_  400
#define U_  64
#define E_  320
#define INNER_ 512
#define VOCAB_ 1024
#define BT_ (B_*T_)      // 1600
#define BU_ (B_*U_)      // 256
#define BTU_ (B_*T_*U_)  // 102400

// Scratch (no allocations allowed -> __device__ globals)
__device__ __half g_Pench[BT_*INNER_];    // 1.6 MB fp16 enc projection
__device__ __half g_Pdech[BU_*INNER_];    // 256 KB fp16 dec projection (+b1 folded)
__device__ __half g_W2h[VOCAB_*INNER_];   // 1.0 MB fp16 W2

// ===========================================================================
// Prologue: proj GEMM (M=64,N=64,K=32 tiles; 232 CTAs) + W2 convert (32 CTAs)
// ===========================================================================
__global__ __launch_bounds__(256) void prologue_kernel(
    const float* __restrict__ enc, const float* __restrict__ dec,
    const float* __restrict__ W1, const float* __restrict__ b1,
    const float* __restrict__ W2)
{
    int cb = blockIdx.x;

    if (cb >= 232) {   // W2 fp32 -> fp16
        int base = (cb - 232) * 16384;
        int tid = threadIdx.x;
        for (int i = tid * 2; i < 16384; i += 512) {
            float2 v = *(const float2*)(W2 + base + i);
            *(__half2*)(g_W2h + base + i) = __floats2half2_rn(v.x, v.y);
        }
        return;
    }

    __shared__ float sx[32 * 68];    // [k][m]
    __shared__ float sw[32 * 68];    // [k][n]
    bool isEnc = cb < 200;
    const float* X; int mt, nt, coff;
    if (isEnc) { mt = cb >> 3;         nt = cb & 7;         X = enc; coff = 0;  }
    else       { mt = (cb - 200) >> 3; nt = (cb - 200) & 7; X = dec; coff = E_; }
    int row0 = mt * 64, col0 = nt * 64;

    int tid = threadIdx.x, tx = tid & 15, ty = tid >> 4;
    float acc[4][4];
    #pragma unroll
    for (int r = 0; r < 4; r++)
        #pragma unroll
        for (int c = 0; c < 4; c++) acc[r][c] = 0.f;

    for (int k0 = 0; k0 < E_; k0 += 32) {
        __syncthreads();
        #pragma unroll
        for (int it = 0; it < 8; it++) {
            int i = tid + it * 256;
            int r = i >> 5, k = i & 31;
            sx[k * 68 + r] = X[(row0 + r) * E_ + k0 + k];
        }
        #pragma unroll
        for (int it = 0; it < 8; it++) {
            int i = tid + it * 256;
            int n = i >> 5, k = i & 31;
            sw[k * 68 + n] = W1[(col0 + n) * (2 * E_) + coff + k0 + k];
        }
        __syncthreads();
        #pragma unroll 8
        for (int k = 0; k < 32; k++) {
            float4 xv = *(const float4*)&sx[k * 68 + ty * 4];
            float4 wv = *(const float4*)&sw[k * 68 + tx * 4];
            float xr[4] = {xv.x, xv.y, xv.z, xv.w};
            float wr[4] = {wv.x, wv.y, wv.z, wv.w};
            #pragma unroll
            for (int r = 0; r < 4; r++)
                #pragma unroll
                for (int c = 0; c < 4; c++)
                    acc[r][c] = fmaf(xr[r], wr[c], acc[r][c]);
        }
    }

    __half* P = isEnc ? g_Pench : g_Pdech;
    #pragma unroll
    for (int r = 0; r < 4; r++) {
        int gr = row0 + ty * 4 + r;
        int cbase = col0 + tx * 4;
        #pragma unroll
        for (int c = 0; c < 4; c += 2) {
            float v0 = acc[r][c], v1 = acc[r][c + 1];
            if (!isEnc) { v0 += b1[cbase + c]; v1 += b1[cbase + c + 1]; }
            *(__half2*)(P + gr * INNER_ + cbase + c) = __floats2half2_rn(v0, v1);
        }
    }
}

// ===========================================================================
// Main fused kernel. M=64 rows/CTA, 256 threads, OCCUPANCY 2 (105 KB SMEM).
// hs[64][512] fp16 = tanh(pe+pd). 64 W2 chunks of (256 vocab x 32 k),
// double-buffered cp.async; m16n8k16 HMMA fp32 acc; +b2 epilogue per vt.
// ===========================================================================
#define HS_STRIDE 520   // halves; row words = 260 == 4 mod 32 -> frag conflict-free
#define WS_STRIDE 40    // halves; row words = 20: frag lanes hit all 32 banks
#define WS_HALVES (256 * WS_STRIDE)
#define SMEM_BYTES ((64 * HS_STRIDE + 2 * WS_HALVES) * (int)sizeof(__half))  // 107520

__device__ __forceinline__ uint32_t smem_u32(const void* p) {
    uint32_t a;
    asm("{ .reg .u64 t; cvta.to.shared.u64 t, %1; cvt.u32.u64 %0, t; }" : "=r"(a) : "l"(p));
    return a;
}
__device__ __forceinline__ uint32_t tanh2(uint32_t x) {
    uint32_t y; asm("tanh.approx.f16x2 %0, %1;" : "=r"(y) : "r"(x)); return y;
}
__device__ __forceinline__ void cp16(uint32_t dst, const void* src) {
    asm volatile("cp.async.cg.shared.global [%0], [%1], 16;" :: "r"(dst), "l"(src) : "memory");
}
__device__ __forceinline__ void mma16816(float* d, const uint32_t* a, const uint32_t* b) {
    asm volatile(
        "mma.sync.aligned.m16n8k16.row.col.f32.f16.f16.f32 "
        "{%0,%1,%2,%3}, {%4,%5,%6,%7}, {%8,%9}, {%0,%1,%2,%3};\n"
        : "+f"(d[0]), "+f"(d[1]), "+f"(d[2]), "+f"(d[3])
        : "r"(a[0]), "r"(a[1]), "r"(a[2]), "r"(a[3]), "r"(b[0]), "r"(b[1]));
}

// stage chunk (vt, kc): 256 vocab rows x 32 k-halves (16 KB), 4x 16B per thread
__device__ __forceinline__ void stage_chunk(uint32_t ws_u32, int chunk, int tid) {
    int vt = chunk >> 4, kc = chunk & 15;
    #pragma unroll
    for (int it = 0; it < 4; it++) {
        int i = tid + it * 256;
        int n = i >> 2, c16 = i & 3;
        cp16(ws_u32 + (n * WS_STRIDE + c16 * 8) * 2,
             g_W2h + (vt * 256 + n) * INNER_ + kc * 32 + c16 * 8);
    }
    asm volatile("cp.async.commit_group;" ::: "memory");
}

__global__ __launch_bounds__(256, 2) void joint_kernel(
    const float* __restrict__ b2, float* __restrict__ out)
{
    extern __shared__ __half smem[];
    __half* hs  = smem;                                  // [64][HS_STRIDE]
    __half* ws0 = smem + 64 * HS_STRIDE;                 // [256][WS_STRIDE]
    __half* ws1 = ws0 + WS_HALVES;

    int tid = threadIdx.x, lane = tid & 31, warp = tid >> 5;
    int row0 = blockIdx.x * 64;
    int b    = row0 / (T_ * U_);
    int bt   = row0 >> 6;                                // constant per CTA

    uint32_t ws_u32[2] = { smem_u32(ws0), smem_u32(ws1) };

    // prefetch chunk 0 (overlaps phase-1 tanh fill)
    stage_chunk(ws_u32[0], 0, tid);

    // ---- Phase 1: hs = tanh(pe + pd) fp16; pe single row, loaded once ----
    {
        const uint32_t* PE = (const uint32_t*)g_Pench;
        const uint32_t* PD = (const uint32_t*)g_Pdech;
        uint32_t pe = PE[bt * 256 + tid];                // tid = half2 column
        #pragma unroll 4
        for (int r = 0; r < 64; r++) {
            uint32_t pd = PD[(b * U_ + r) * 256 + tid];
            __half2 s = __hadd2(*(__half2*)&pe, *(__half2*)&pd);
            *(uint32_t*)(hs + r * HS_STRIDE + tid * 2) = tanh2(*(uint32_t*)&s);
        }
    }

    int wm = warp & 1;                 // 2 row groups of 32
    int wn = warp >> 1;                // 4 vocab groups of 64
    int arow = wm * 32 + (lane >> 2);
    int acb  = (lane & 3) * 2;
    int bnb  = wn * 64 + (lane >> 2);

    float acc[2][8][4];
    #pragma unroll
    for (int mi = 0; mi < 2; mi++)
        #pragma unroll
        for (int ni = 0; ni < 8; ni++)
            #pragma unroll
            for (int q = 0; q < 4; q++) acc[mi][ni][q] = 0.f;

    for (int ch = 0; ch < 64; ch++) {
        int vt = ch >> 4, kc = ch & 15;
        __syncthreads();   // prev compute done (or phase-1 on ch==0)
        if (ch + 1 < 64) stage_chunk(ws_u32[(ch + 1) & 1], ch + 1, tid);
        if (ch + 1 < 64) asm volatile("cp.async.wait_group 1;" ::: "memory");
        else             asm volatile("cp.async.wait_group 0;" ::: "memory");
        __syncthreads();   // chunk ch visible

        const __half* ws = (ch & 1) ? ws1 : ws0;

        #pragma unroll
        for (int ks = 0; ks < 32; ks += 16) {
            int kx = kc * 32 + ks + acb;     // hs column (global k)
            uint32_t a[2][4];
            #pragma unroll
            for (int mi = 0; mi < 2; mi++) {
                const __half* base  = hs + (arow + mi * 16) * HS_STRIDE;
                const __half* base8 = base + 8 * HS_STRIDE;
                a[mi][0] = *(const uint32_t*)(base  + kx);
                a[mi][1] = *(const uint32_t*)(base8 + kx);
                a[mi][2] = *(const uint32_t*)(base  + kx + 8);
                a[mi][3] = *(const uint32_t*)(base8 + kx + 8);
            }
            uint32_t bf[8][2];
            #pragma unroll
            for (int ni = 0; ni < 8; ni++) {
                const __half* wb = ws + (bnb + ni * 8) * WS_STRIDE + ks + acb;
                bf[ni][0] = *(const uint32_t*)(wb);
                bf[ni][1] = *(const uint32_t*)(wb + 8);
            }
            #pragma unroll
            for (int mi = 0; mi < 2; mi++)
                #pragma unroll
                for (int ni = 0; ni < 8; ni++)
                    mma16816(acc[mi][ni], a[mi], bf[ni]);
        }

        if (kc == 15) {
            // ---- Epilogue for vt: += b2, store fp32, reset acc ----
            #pragma unroll
            for (int mi = 0; mi < 2; mi++) {
                #pragma unroll
                for (int ni = 0; ni < 8; ni++) {
                    int m = row0 + wm * 32 + mi * 16 + (lane >> 2);
                    int n = vt * 256 + wn * 64 + ni * 8 + (lane & 3) * 2;
                    float2 bb = *(const float2*)(b2 + n);
                    float2 v0 = make_float2(acc[mi][ni][0] + bb.x, acc[mi][ni][1] + bb.y);
                    float2 v1 = make_float2(acc[mi][ni][2] + bb.x, acc[mi][ni][3] + bb.y);
                    *(float2*)(out + (size_t)m       * VOCAB_ + n) = v0;
                    *(float2*)(out + (size_t)(m + 8) * VOCAB_ + n) = v1;
                    #pragma unroll
                    for (int q = 0; q < 4; q++) acc[mi][ni][q] = 0.f;
                }
            }
        }
    }
}

// ===========================================================================
extern "C" void kernel_launch(void* const* d_in, const int* in_sizes, int n_in,
                              void* d_out, int out_size)
{
    const float* enc = (const float*)d_in[0];
    const float* dec = (const float*)d_in[1];
    const float* W1  = (const float*)d_in[2];
    const float* b1  = (const float*)d_in[3];
    const float* W2  = (const float*)d_in[4];
    const float* b2  = (const float*)d_in[5];
    float* out = (float*)d_out;

    cudaFuncSetAttribute(joint_kernel,
                         cudaFuncAttributeMaxDynamicSharedMemorySize, SMEM_BYTES);

    prologue_kernel<<<264, 256>>>(enc, dec, W1, b1, W2);
    joint_kernel<<<BTU_/64, 256, SMEM_BYTES>>>(b2, out);
}

// round 8
// speedup vs baseline: 1.0974x; 1.0019x over previous
#include <cuda_runtime.h>
#include <cuda_fp16.h>
#include <cstdint>

#define B_  4
#define T_  400
#define U_  64
#define E_  320
#define INNER_ 512
#define VOCAB_ 1024
#define BT_ (B_*T_)      // 1600
#define BU_ (B_*U_)      // 256
#define BTU_ (B_*T_*U_)  // 102400

// Scratch (no allocations allowed -> __device__ globals)
__device__ __half g_Pench[BT_*INNER_];    // 1.6 MB fp16 enc projection
__device__ __half g_Pdech[BU_*INNER_];    // 256 KB fp16 dec projection (+b1 folded)
__device__ __half g_W2h[VOCAB_*INNER_];   // 1.0 MB fp16 W2

// ===========================================================================
// Prologue: proj GEMM (M=64,N=64,K=32 tiles; 232 CTAs) + W2 convert (32 CTAs)
// ===========================================================================
__global__ __launch_bounds__(256) void prologue_kernel(
    const float* __restrict__ enc, const float* __restrict__ dec,
    const float* __restrict__ W1, const float* __restrict__ b1,
    const float* __restrict__ W2)
{
    int cb = blockIdx.x;

    if (cb >= 232) {   // W2 fp32 -> fp16
        int base = (cb - 232) * 16384;
        int tid = threadIdx.x;
        for (int i = tid * 2; i < 16384; i += 512) {
            float2 v = *(const float2*)(W2 + base + i);
            *(__half2*)(g_W2h + base + i) = __floats2half2_rn(v.x, v.y);
        }
        return;
    }

    __shared__ float sx[32 * 68];    // [k][m]
    __shared__ float sw[32 * 68];    // [k][n]
    bool isEnc = cb < 200;
    const float* X; int mt, nt, coff;
    if (isEnc) { mt = cb >> 3;         nt = cb & 7;         X = enc; coff = 0;  }
    else       { mt = (cb - 200) >> 3; nt = (cb - 200) & 7; X = dec; coff = E_; }
    int row0 = mt * 64, col0 = nt * 64;

    int tid = threadIdx.x, tx = tid & 15, ty = tid >> 4;
    float acc[4][4];
    #pragma unroll
    for (int r = 0; r < 4; r++)
        #pragma unroll
        for (int c = 0; c < 4; c++) acc[r][c] = 0.f;

    for (int k0 = 0; k0 < E_; k0 += 32) {
        __syncthreads();
        #pragma unroll
        for (int it = 0; it < 8; it++) {
            int i = tid + it * 256;
            int r = i >> 5, k = i & 31;
            sx[k * 68 + r] = X[(row0 + r) * E_ + k0 + k];
        }
        #pragma unroll
        for (int it = 0; it < 8; it++) {
            int i = tid + it * 256;
            int n = i >> 5, k = i & 31;
            sw[k * 68 + n] = W1[(col0 + n) * (2 * E_) + coff + k0 + k];
        }
        __syncthreads();
        #pragma unroll 8
        for (int k = 0; k < 32; k++) {
            float4 xv = *(const float4*)&sx[k * 68 + ty * 4];
            float4 wv = *(const float4*)&sw[k * 68 + tx * 4];
            float xr[4] = {xv.x, xv.y, xv.z, xv.w};
            float wr[4] = {wv.x, wv.y, wv.z, wv.w};
            #pragma unroll
            for (int r = 0; r < 4; r++)
                #pragma unroll
                for (int c = 0; c < 4; c++)
                    acc[r][c] = fmaf(xr[r], wr[c], acc[r][c]);
        }
    }

    __half* P = isEnc ? g_Pench : g_Pdech;
    #pragma unroll
    for (int r = 0; r < 4; r++) {
        int gr = row0 + ty * 4 + r;
        int cbase = col0 + tx * 4;
        #pragma unroll
        for (int c = 0; c < 4; c += 2) {
            float v0 = acc[r][c], v1 = acc[r][c + 1];
            if (!isEnc) { v0 += b1[cbase + c]; v1 += b1[cbase + c + 1]; }
            *(__half2*)(P + gr * INNER_ + cbase + c) = __floats2half2_rn(v0, v1);
        }
    }
}

// ===========================================================================
// Main fused kernel. M=64 rows/CTA, 256 threads, OCCUPANCY 2 (105 KB SMEM,
// carveout forced to max 228 KB so two CTAs co-reside).
// hs[64][512] fp16 = tanh(pe+pd). 64 W2 chunks of (256 vocab x 32 k),
// double-buffered cp.async; m16n8k16 HMMA fp32 acc; +b2 epilogue per vt.
// ===========================================================================
#define HS_STRIDE 520   // halves; row words = 260 == 4 mod 32 -> frag conflict-free
#define WS_STRIDE 40    // halves; row words = 20: frag lanes hit all 32 banks
#define WS_HALVES (256 * WS_STRIDE)
#define SMEM_BYTES ((64 * HS_STRIDE + 2 * WS_HALVES) * (int)sizeof(__half))  // 107520

__device__ __forceinline__ uint32_t smem_u32(const void* p) {
    uint32_t a;
    asm("{ .reg .u64 t; cvta.to.shared.u64 t, %1; cvt.u32.u64 %0, t; }" : "=r"(a) : "l"(p));
    return a;
}
__device__ __forceinline__ uint32_t tanh2(uint32_t x) {
    uint32_t y; asm("tanh.approx.f16x2 %0, %1;" : "=r"(y) : "r"(x)); return y;
}
__device__ __forceinline__ void cp16(uint32_t dst, const void* src) {
    asm volatile("cp.async.cg.shared.global [%0], [%1], 16;" :: "r"(dst), "l"(src) : "memory");
}
__device__ __forceinline__ void mma16816(float* d, const uint32_t* a, const uint32_t* b) {
    asm volatile(
        "mma.sync.aligned.m16n8k16.row.col.f32.f16.f16.f32 "
        "{%0,%1,%2,%3}, {%4,%5,%6,%7}, {%8,%9}, {%0,%1,%2,%3};\n"
        : "+f"(d[0]), "+f"(d[1]), "+f"(d[2]), "+f"(d[3])
        : "r"(a[0]), "r"(a[1]), "r"(a[2]), "r"(a[3]), "r"(b[0]), "r"(b[1]));
}

// stage chunk (vt, kc): 256 vocab rows x 32 k-halves (16 KB), 4x 16B per thread
__device__ __forceinline__ void stage_chunk(uint32_t ws_u32, int chunk, int tid) {
    int vt = chunk >> 4, kc = chunk & 15;
    #pragma unroll
    for (int it = 0; it < 4; it++) {
        int i = tid + it * 256;
        int n = i >> 2, c16 = i & 3;
        cp16(ws_u32 + (n * WS_STRIDE + c16 * 8) * 2,
             g_W2h + (vt * 256 + n) * INNER_ + kc * 32 + c16 * 8);
    }
    asm volatile("cp.async.commit_group;" ::: "memory");
}

__global__ __launch_bounds__(256, 2) void joint_kernel(
    const float* __restrict__ b2, float* __restrict__ out)
{
    extern __shared__ __half smem[];
    __half* hs  = smem;                                  // [64][HS_STRIDE]
    __half* ws0 = smem + 64 * HS_STRIDE;                 // [256][WS_STRIDE]
    __half* ws1 = ws0 + WS_HALVES;

    int tid = threadIdx.x, lane = tid & 31, warp = tid >> 5;
    int row0 = blockIdx.x * 64;
    int b    = row0 / (T_ * U_);
    int bt   = row0 >> 6;                                // constant per CTA

    uint32_t ws_u32[2] = { smem_u32(ws0), smem_u32(ws1) };

    // prefetch chunk 0 (overlaps phase-1 tanh fill)
    stage_chunk(ws_u32[0], 0, tid);

    // ---- Phase 1: hs = tanh(pe + pd) fp16; pe single row, loaded once ----
    {
        const uint32_t* PE = (const uint32_t*)g_Pench;
        const uint32_t* PD = (const uint32_t*)g_Pdech;
        uint32_t pe = PE[bt * 256 + tid];                // tid = half2 column
        #pragma unroll 4
        for (int r = 0; r < 64; r++) {
            uint32_t pd = PD[(b * U_ + r) * 256 + tid];
            __half2 s = __hadd2(*(__half2*)&pe, *(__half2*)&pd);
            *(uint32_t*)(hs + r * HS_STRIDE + tid * 2) = tanh2(*(uint32_t*)&s);
        }
    }

    int wm = warp & 1;                 // 2 row groups of 32
    int wn = warp >> 1;                // 4 vocab groups of 64
    int arow = wm * 32 + (lane >> 2);
    int acb  = (lane & 3) * 2;
    int bnb  = wn * 64 + (lane >> 2);

    float acc[2][8][4];
    #pragma unroll
    for (int mi = 0; mi < 2; mi++)
        #pragma unroll
        for (int ni = 0; ni < 8; ni++)
            #pragma unroll
            for (int q = 0; q < 4; q++) acc[mi][ni][q] = 0.f;

    for (int ch = 0; ch < 64; ch++) {
        int vt = ch >> 4, kc = ch & 15;
        __syncthreads();   // prev compute done (or phase-1 on ch==0)
        if (ch + 1 < 64) stage_chunk(ws_u32[(ch + 1) & 1], ch + 1, tid);
        if (ch + 1 < 64) asm volatile("cp.async.wait_group 1;" ::: "memory");
        else             asm volatile("cp.async.wait_group 0;" ::: "memory");
        __syncthreads();   // chunk ch visible

        const __half* ws = (ch & 1) ? ws1 : ws0;

        #pragma unroll
        for (int ks = 0; ks < 32; ks += 16) {
            int kx = kc * 32 + ks + acb;     // hs column (global k)
            uint32_t a[2][4];
            #pragma unroll
            for (int mi = 0; mi < 2; mi++) {
                const __half* base  = hs + (arow + mi * 16) * HS_STRIDE;
                const __half* base8 = base + 8 * HS_STRIDE;
                a[mi][0] = *(const uint32_t*)(base  + kx);
                a[mi][1] = *(const uint32_t*)(base8 + kx);
                a[mi][2] = *(const uint32_t*)(base  + kx + 8);
                a[mi][3] = *(const uint32_t*)(base8 + kx + 8);
            }
            uint32_t bf[8][2];
            #pragma unroll
            for (int ni = 0; ni < 8; ni++) {
                const __half* wb = ws + (bnb + ni * 8) * WS_STRIDE + ks + acb;
                bf[ni][0] = *(const uint32_t*)(wb);
                bf[ni][1] = *(const uint32_t*)(wb + 8);
            }
            #pragma unroll
            for (int mi = 0; mi < 2; mi++)
                #pragma unroll
                for (int ni = 0; ni < 8; ni++)
                    mma16816(acc[mi][ni], a[mi], bf[ni]);
        }

        if (kc == 15) {
            // ---- Epilogue for vt: += b2, store fp32, reset acc ----
            #pragma unroll
            for (int mi = 0; mi < 2; mi++) {
                #pragma unroll
                for (int ni = 0; ni < 8; ni++) {
                    int m = row0 + wm * 32 + mi * 16 + (lane >> 2);
                    int n = vt * 256 + wn * 64 + ni * 8 + (lane & 3) * 2;
                    float2 bb = *(const float2*)(b2 + n);
                    float2 v0 = make_float2(acc[mi][ni][0] + bb.x, acc[mi][ni][1] + bb.y);
                    float2 v1 = make_float2(acc[mi][ni][2] + bb.x, acc[mi][ni][3] + bb.y);
                    *(float2*)(out + (size_t)m       * VOCAB_ + n) = v0;
                    *(float2*)(out + (size_t)(m + 8) * VOCAB_ + n) = v1;
                    #pragma unroll
                    for (int q = 0; q < 4; q++) acc[mi][ni][q] = 0.f;
                }
            }
        }
    }
}

// ===========================================================================
extern "C" void kernel_launch(void* const* d_in, const int* in_sizes, int n_in,
                              void* d_out, int out_size)
{
    const float* enc = (const float*)d_in[0];
    const float* dec = (const float*)d_in[1];
    const float* W1  = (const float*)d_in[2];
    const float* b1  = (const float*)d_in[3];
    const float* W2  = (const float*)d_in[4];
    const float* b2  = (const float*)d_in[5];
    float* out = (float*)d_out;

    cudaFuncSetAttribute(joint_kernel,
                         cudaFuncAttributeMaxDynamicSharedMemorySize, SMEM_BYTES);
    // Force max shared-memory carveout (228 KB). Without this the driver picks
    // the smallest bucket >= one CTA's 107.5 KB (=132 KB), capping occupancy at 1.
    cudaFuncSetAttribute(joint_kernel,
                         cudaFuncAttributePreferredSharedMemoryCarveout, 100);

    prologue_kernel<<<264, 256>>>(enc, dec, W1, b1, W2);
    joint_kernel<<<BTU_/64, 256, SMEM_BYTES>>>(b2, out);
}